// round 8
// baseline (speedup 1.0000x reference)
#include <cuda_runtime.h>
#include <math.h>

#define B_    2
#define CIN   32
#define COUT  32
#define D_    40
#define E_    3
#define SP    (D_*D_*D_)          // 64000
#define YTOT  (B_*COUT*SP)        // 4,096,000
#define OCG   4                   // output channels per block
#define NOCG  (COUT/OCG)          // 8
#define SROW  48                  // padded smem row stride (floats)
#define NROWS (3*42)              // 126 rows (3 z-planes x 42 y-rows)
#define SLABVOL (NROWS*SROW)      // 6048 floats
#define WBLK  (CIN*27*OCG)        // 3456 weights per block
#define WICS  (27*OCG)            // 108 weights per ic

typedef unsigned long long u64_t;

// ---- scratch (device globals; no runtime allocation) ----
__device__ float g_w[B_*NOCG*WBLK];     // [b][ocg][ic][ky][dz][kx][oc4]
__device__ float g_bias[B_*COUT];
__device__ float g_y[YTOT];             // pre-upsample activations (16.4 MB)
__device__ float g_sum[COUT];
__device__ float g_sumsq[COUT];
__device__ float g_scale[COUT];
__device__ float g_shift[COUT];

// ---- packed fp32x2 helpers (Blackwell FFMA2 via PTX) ----
__device__ __forceinline__ u64_t pk2(float v) {
    u64_t r; asm("mov.b64 %0, {%1,%1};" : "=l"(r) : "f"(v)); return r;
}
__device__ __forceinline__ void ffma2(u64_t& d, u64_t a, u64_t b) {
    asm("fma.rn.f32x2 %0, %1, %2, %0;" : "+l"(d) : "l"(a), "l"(b));
}
__device__ __forceinline__ float lo32(u64_t v) { return __uint_as_float((unsigned)v); }
__device__ __forceinline__ float hi32(u64_t v) { return __uint_as_float((unsigned)(v >> 32)); }

// ---------------------------------------------------------------------------
// Kernel 1: routing + combined weights (blocked layout) + bias, zero stats
// ---------------------------------------------------------------------------
__global__ void k_route(const float* __restrict__ emb,
                        const float* __restrict__ rw,
                        const float* __restrict__ rb,
                        const float* __restrict__ ek,
                        const float* __restrict__ eb) {
    float r[B_][E_];
    #pragma unroll
    for (int b = 0; b < B_; b++)
        #pragma unroll
        for (int e = 0; e < E_; e++) {
            float t = fmaf(emb[b], rw[e], rb[e]);
            r[b][e] = 1.0f / (1.0f + expf(-t));
        }

    int idx = blockIdx.x * blockDim.x + threadIdx.x;
    const int TOT = B_ * NOCG * WBLK;   // 55296
    if (idx < TOT) {
        int rr = idx;
        int og = rr & 3;  rr >>= 2;
        int kx = rr % 3;  rr /= 3;
        int dz = rr % 3;  rr /= 3;
        int ky = rr % 3;  rr /= 3;
        int ic = rr % CIN; rr /= CIN;
        int ocg = rr % NOCG;
        int b   = rr / NOCG;
        int oc  = ocg * OCG + og;
        int tap = dz * 9 + ky * 3 + kx;
        float s = 0.0f;
        #pragma unroll
        for (int e = 0; e < E_; e++)
            s = fmaf(r[b][e], ek[((e * COUT + oc) * CIN + ic) * 27 + tap], s);
        g_w[idx] = s;
    }
    if (idx < B_ * COUT) {
        int b = idx / COUT, o = idx - b * COUT;
        float s = 0.0f;
        #pragma unroll
        for (int e = 0; e < E_; e++) s = fmaf(r[b][e], eb[e * COUT + o], s);
        g_bias[idx] = s;
    }
    if (idx < COUT) { g_sum[idx] = 0.0f; g_sumsq[idx] = 0.0f; }
}

// ---------------------------------------------------------------------------
// Kernel 2: direct 3x3x3 conv, 4 oc per block, packed FFMA2 inner loop.
//   Aligned pairs q[k]=(f[2k+1],f[2k+2]); accA (kx=1) + accB (kx=0,2) + edges.
// grid = (40 z, 8 ocg, 2 b), block = 224 (t<200 compute, t<126 load rows)
// ---------------------------------------------------------------------------
__global__ void __launch_bounds__(224, 2)
k_conv(const float* __restrict__ x) {
    extern __shared__ float dyn[];
    float* sh  = dyn;                    // [2][SLABVOL]
    float* wsh = dyn + 2 * SLABVOL;      // [WBLK]
    float* red = wsh + WBLK;             // [64]

    const int z0  = blockIdx.x;           // output z, 0..39
    const int ocg = blockIdx.y;           // 0..7
    const int b   = blockIdx.z;           // 0..1
    const int t   = threadIdx.x;

    // zero slabs once: halo rows/cols stay zero for all ic
    for (int i = t; i < 2 * SLABVOL; i += 224) dyn[i] = 0.0f;
    const float* gw = g_w + (size_t)(b * NOCG + ocg) * WBLK;
    for (int i = t; i < WBLK; i += 224) wsh[i] = gw[i];

    // ---- loader: one smem row per thread (t < 126), 10 x 16B cp.async ----
    const float* xb = x + (size_t)(b * CIN) * SP;
    const int lz = t / 42, ly = t - 42 * (t / 42);
    const int gz = z0 - 1 + lz, gy = ly - 1;
    const bool rowok = (t < NROWS) && ((unsigned)gz < D_) && ((unsigned)gy < D_);
    const long grow = (long)gz * 1600 + (long)gy * 40;
    const unsigned sdst0 = (unsigned)__cvta_generic_to_shared(sh)
                         + (unsigned)(t * (SROW * 4) + 16);   // word 4, 16B aligned

    auto prefetch = [&](int ic, int buf) {
        if (!rowok) return;
        const float* src = xb + (size_t)ic * SP + grow;
        unsigned d = sdst0 + (unsigned)buf * (SLABVOL * 4);
        #pragma unroll
        for (int c = 0; c < 10; c++)
            asm volatile("cp.async.cg.shared.global [%0], [%1], 16;"
                         :: "r"(d + c * 16), "l"(src + c * 4));
    };

    // ---- compute setup ----
    const int ty = t / 5;                 // 0..39
    const int xs = (t % 5) * 8;           // 0,8,16,24,32
    const bool active = (t < 200);

    // per oc: accA[4] pairs (out0,1),(2,3),(4,5),(6,7); accB[3] (1,2),(3,4),(5,6)
    u64_t accA[OCG][4], accB[OCG][3];
    float accS0[OCG], accS7[OCG];
    #pragma unroll
    for (int og = 0; og < OCG; og++) {
        #pragma unroll
        for (int j = 0; j < 4; j++) accA[og][j] = 0ull;
        #pragma unroll
        for (int j = 0; j < 3; j++) accB[og][j] = 0ull;
        accS0[og] = 0.0f; accS7[og] = 0.0f;
    }

    __syncthreads();            // zero-fill visible before first prefetch
    prefetch(0, 0);
    asm volatile("cp.async.commit_group;");

    for (int ic = 0; ic < CIN; ic++) {
        __syncthreads();
        if (ic + 1 < CIN) prefetch(ic + 1, (ic + 1) & 1);
        asm volatile("cp.async.commit_group;");
        asm volatile("cp.async.wait_group 1;");
        __syncthreads();

        if (active) {
            const float* S = sh + (ic & 1) * SLABVOL;
            const float* W = wsh + ic * WICS;   // [ky][zz][kx][oc4]
            #pragma unroll 1
            for (int ky = 0; ky < 3; ky++) {
                #pragma unroll
                for (int zz = 0; zz < 3; zz++) {
                    // window: input cols xs-1 .. xs+8 => smem words 3+xs .. 12+xs
                    const float* rowp = S + (zz * 42 + ty + ky) * SROW + 3 + xs;
                    float f0 = rowp[0];
                    float f9 = rowp[9];
                    u64_t q[4];                 // (f1,f2)(f3,f4)(f5,f6)(f7,f8)
                    float4 a = *(const float4*)(rowp + 1);   // word 4+xs: 16B aligned
                    float4 c4 = *(const float4*)(rowp + 5);
                    q[0] = ((u64_t)__float_as_uint(a.y) << 32) | __float_as_uint(a.x);
                    q[1] = ((u64_t)__float_as_uint(a.w) << 32) | __float_as_uint(a.z);
                    q[2] = ((u64_t)__float_as_uint(c4.y) << 32) | __float_as_uint(c4.x);
                    q[3] = ((u64_t)__float_as_uint(c4.w) << 32) | __float_as_uint(c4.z);
                    float f2 = a.y, f7 = c4.z;

                    const float4 w0 = *(const float4*)(W + ((ky * 3 + zz) * 3 + 0) * 4);
                    const float4 w1 = *(const float4*)(W + ((ky * 3 + zz) * 3 + 1) * 4);
                    const float4 w2 = *(const float4*)(W + ((ky * 3 + zz) * 3 + 2) * 4);
                    const float w0s[OCG] = {w0.x, w0.y, w0.z, w0.w};
                    const float w1s[OCG] = {w1.x, w1.y, w1.z, w1.w};
                    const float w2s[OCG] = {w2.x, w2.y, w2.z, w2.w};
                    #pragma unroll
                    for (int og = 0; og < OCG; og++) {
                        const u64_t w0p = pk2(w0s[og]);
                        const u64_t w1p = pk2(w1s[og]);
                        const u64_t w2p = pk2(w2s[og]);
                        // kx=1: out[j] += w1*f[j+1] -> accA pairs use q[i]
                        #pragma unroll
                        for (int i = 0; i < 4; i++) ffma2(accA[og][i], q[i], w1p);
                        // kx=0: out[j] += w0*f[j] -> accB pairs use q[i]
                        #pragma unroll
                        for (int i = 0; i < 3; i++) ffma2(accB[og][i], q[i], w0p);
                        // kx=2: out[j] += w2*f[j+2] -> accB pairs use q[i+1]
                        #pragma unroll
                        for (int i = 0; i < 3; i++) ffma2(accB[og][i], q[i + 1], w2p);
                        // edges
                        accS0[og] = fmaf(w0s[og], f0, accS0[og]);
                        accS0[og] = fmaf(w2s[og], f2, accS0[og]);
                        accS7[og] = fmaf(w0s[og], f7, accS7[og]);
                        accS7[og] = fmaf(w2s[og], f9, accS7[og]);
                    }
                }
            }
        }
    }

    // ---- epilogue: merge, bias, store y, BN partial sums (per og) ----
    float s1[OCG], s2[OCG];
    #pragma unroll
    for (int og = 0; og < OCG; og++) { s1[og] = 0.0f; s2[og] = 0.0f; }

    if (active) {
        #pragma unroll
        for (int og = 0; og < OCG; og++) {
            const int oc = ocg * OCG + og;
            const float bias = g_bias[b * COUT + oc];
            float* yp = g_y + (size_t)(b * COUT + oc) * SP + z0 * 1600 + ty * 40 + xs;
            float o[8];
            o[0] = lo32(accA[og][0]) + accS0[og];
            o[1] = hi32(accA[og][0]) + lo32(accB[og][0]);
            o[2] = lo32(accA[og][1]) + hi32(accB[og][0]);
            o[3] = hi32(accA[og][1]) + lo32(accB[og][1]);
            o[4] = lo32(accA[og][2]) + hi32(accB[og][1]);
            o[5] = hi32(accA[og][2]) + lo32(accB[og][2]);
            o[6] = lo32(accA[og][3]) + hi32(accB[og][2]);
            o[7] = hi32(accA[og][3]) + accS7[og];
            float4 q0, q1; float v;
            v = o[0] + bias; s1[og] += v; s2[og] = fmaf(v, v, s2[og]); q0.x = v;
            v = o[1] + bias; s1[og] += v; s2[og] = fmaf(v, v, s2[og]); q0.y = v;
            v = o[2] + bias; s1[og] += v; s2[og] = fmaf(v, v, s2[og]); q0.z = v;
            v = o[3] + bias; s1[og] += v; s2[og] = fmaf(v, v, s2[og]); q0.w = v;
            v = o[4] + bias; s1[og] += v; s2[og] = fmaf(v, v, s2[og]); q1.x = v;
            v = o[5] + bias; s1[og] += v; s2[og] = fmaf(v, v, s2[og]); q1.y = v;
            v = o[6] + bias; s1[og] += v; s2[og] = fmaf(v, v, s2[og]); q1.z = v;
            v = o[7] + bias; s1[og] += v; s2[og] = fmaf(v, v, s2[og]); q1.w = v;
            *(float4*)yp       = q0;
            *(float4*)(yp + 4) = q1;
        }
    }
    #pragma unroll
    for (int og = 0; og < OCG; og++) {
        #pragma unroll
        for (int o = 16; o > 0; o >>= 1) {
            s1[og] += __shfl_down_sync(0xffffffff, s1[og], o);
            s2[og] += __shfl_down_sync(0xffffffff, s2[og], o);
        }
    }
    const int wid = t >> 5, lane = t & 31;
    __syncthreads();
    if (lane == 0) {
        #pragma unroll
        for (int og = 0; og < OCG; og++) {
            red[og * 8 + wid]      = s1[og];
            red[32 + og * 8 + wid] = s2[og];
        }
    }
    __syncthreads();
    if (t < OCG) {
        float a = 0.0f, q = 0.0f;
        #pragma unroll
        for (int i = 0; i < 7; i++) { a += red[t * 8 + i]; q += red[32 + t * 8 + i]; }
        atomicAdd(&g_sum[ocg * OCG + t], a);
        atomicAdd(&g_sumsq[ocg * OCG + t], q);
    }
}

// ---------------------------------------------------------------------------
// Kernel 3: finalize BN -> per-channel scale/shift
// ---------------------------------------------------------------------------
__global__ void k_stats(const float* __restrict__ gamma,
                        const float* __restrict__ beta) {
    int c = threadIdx.x;
    if (c < COUT) {
        const float n = (float)(B_ * SP);
        float mean = g_sum[c] / n;
        float var  = g_sumsq[c] / n - mean * mean;
        float sc = gamma[c] * rsqrtf(var + 1e-5f);
        g_scale[c] = sc;
        g_shift[c] = beta[c] - mean * sc;
    }
}

// ---------------------------------------------------------------------------
// Kernel 4: affine + LeakyReLU + nearest upsample x2; float2 in, 4x float4 out
// ---------------------------------------------------------------------------
__global__ void __launch_bounds__(256)
k_up(float* __restrict__ out) {
    int idx = blockIdx.x * blockDim.x + threadIdx.x;  // over YTOT/2
    if (idx >= YTOT / 2) return;
    int i2 = idx * 2;
    int xw = i2 % 40;                 // even
    int rest = i2 / 40;
    int yw = rest % 40; rest /= 40;
    int zw = rest % 40; rest /= 40;
    int c  = rest % COUT;
    int b  = rest / COUT;

    float2 v = *(const float2*)&g_y[i2];
    float sc = g_scale[c], sf = g_shift[c];
    float a0 = fmaf(sc, v.x, sf); a0 = (a0 >= 0.0f) ? a0 : 0.1f * a0;
    float a1 = fmaf(sc, v.y, sf); a1 = (a1 >= 0.0f) ? a1 : 0.1f * a1;
    float4 p = make_float4(a0, a0, a1, a1);

    size_t base = ((size_t)(b * COUT + c) * 512000u)
                + (size_t)(2 * zw) * 6400u + (size_t)(2 * yw) * 80u + (size_t)(2 * xw);
    float4* o4 = (float4*)(out + base);
    o4[0]    = p;    // (2z,   2y  )
    o4[20]   = p;    // (2z,   2y+1)
    o4[1600] = p;    // (2z+1, 2y  )
    o4[1620] = p;    // (2z+1, 2y+1)
}

// ---------------------------------------------------------------------------
extern "C" void kernel_launch(void* const* d_in, const int* in_sizes, int n_in,
                              void* d_out, int out_size) {
    const float* x     = (const float*)d_in[0];
    const float* emb   = (const float*)d_in[1];
    const float* rw    = (const float*)d_in[2];
    const float* rb    = (const float*)d_in[3];
    const float* ek    = (const float*)d_in[4];
    const float* eb    = (const float*)d_in[5];
    const float* gamma = (const float*)d_in[6];
    const float* beta  = (const float*)d_in[7];
    float* out = (float*)d_out;

    k_route<<<(B_ * NOCG * WBLK + 255) / 256, 256>>>(emb, rw, rb, ek, eb);

    size_t shbytes = (size_t)(2 * SLABVOL + WBLK + 64) * sizeof(float);  // ~62.5 KB
    cudaFuncSetAttribute(k_conv, cudaFuncAttributeMaxDynamicSharedMemorySize, (int)shbytes);
    dim3 gconv(D_, NOCG, B_);
    k_conv<<<gconv, 224, shbytes>>>(x);

    k_stats<<<1, 32>>>(gamma, beta);

    k_up<<<(YTOT / 2 + 255) / 256, 256>>>(out);
}

// round 9
// speedup vs baseline: 1.3331x; 1.3331x over previous
#include <cuda_runtime.h>
#include <math.h>

#define B_    2
#define CIN   32
#define COUT  32
#define D_    40
#define E_    3
#define SP    (D_*D_*D_)          // 64000
#define YTOT  (B_*COUT*SP)        // 4,096,000
#define OCG   4                   // output channels per block
#define NOCG  (COUT/OCG)          // 8
#define YT    20                  // y-rows per block (2 tiles cover 40)
#define SROW  48                  // padded smem row stride (floats)
#define NROWS (3*(YT+2))          // 66 rows (3 z-planes x 22 y-rows)
#define SLABVOL (NROWS*SROW)      // 3168 floats
#define WBLK  (CIN*27*OCG)        // 3456 weights per block
#define WICS  (27*OCG)            // 108 weights per ic

// ---- scratch (device globals; no runtime allocation) ----
__device__ float g_w[B_*NOCG*WBLK];     // [b][ocg][ic][ky][dz][kx][oc4]
__device__ float g_bias[B_*COUT];
__device__ float g_y[YTOT];             // pre-upsample activations (16.4 MB)
__device__ float g_sum[COUT];
__device__ float g_sumsq[COUT];
__device__ float g_scale[COUT];
__device__ float g_shift[COUT];

// ---------------------------------------------------------------------------
// Kernel 1: routing + combined weights (blocked layout) + bias, zero stats
// ---------------------------------------------------------------------------
__global__ void k_route(const float* __restrict__ emb,
                        const float* __restrict__ rw,
                        const float* __restrict__ rb,
                        const float* __restrict__ ek,
                        const float* __restrict__ eb) {
    float r[B_][E_];
    #pragma unroll
    for (int b = 0; b < B_; b++)
        #pragma unroll
        for (int e = 0; e < E_; e++) {
            float t = fmaf(emb[b], rw[e], rb[e]);
            r[b][e] = 1.0f / (1.0f + expf(-t));
        }

    int idx = blockIdx.x * blockDim.x + threadIdx.x;
    const int TOT = B_ * NOCG * WBLK;   // 55296
    if (idx < TOT) {
        int rr = idx;
        int og = rr & 3;  rr >>= 2;
        int kx = rr % 3;  rr /= 3;
        int dz = rr % 3;  rr /= 3;
        int ky = rr % 3;  rr /= 3;
        int ic = rr % CIN; rr /= CIN;
        int ocg = rr % NOCG;
        int b   = rr / NOCG;
        int oc  = ocg * OCG + og;
        int tap = dz * 9 + ky * 3 + kx;
        float s = 0.0f;
        #pragma unroll
        for (int e = 0; e < E_; e++)
            s = fmaf(r[b][e], ek[((e * COUT + oc) * CIN + ic) * 27 + tap], s);
        g_w[idx] = s;
    }
    if (idx < B_ * COUT) {
        int b = idx / COUT, o = idx - b * COUT;
        float s = 0.0f;
        #pragma unroll
        for (int e = 0; e < E_; e++) s = fmaf(r[b][e], eb[e * COUT + o], s);
        g_bias[idx] = s;
    }
    if (idx < COUT) { g_sum[idx] = 0.0f; g_sumsq[idx] = 0.0f; }
}

// ---------------------------------------------------------------------------
// Kernel 2: direct 3x3x3 conv, 4 oc per block, y split in 2 tiles of 20.
// grid = (80 [z*2+yhalf], 8 ocg, 2 b) = 1280 blocks; block = 128 threads
//   t<100 compute (20 y x 5 x-tiles), t<66 load rows (3 z x 22 y)
// ---------------------------------------------------------------------------
__global__ void __launch_bounds__(128, 4)
k_conv(const float* __restrict__ x) {
    extern __shared__ float dyn[];
    float* sh  = dyn;                    // [2][SLABVOL]
    float* wsh = dyn + 2 * SLABVOL;      // [WBLK]
    float* red = wsh + WBLK;             // [32]

    const int z0  = blockIdx.x >> 1;            // 0..39
    const int yh  = (blockIdx.x & 1) * YT;      // 0 or 20
    const int ocg = blockIdx.y;                 // 0..7
    const int b   = blockIdx.z;                 // 0..1
    const int t   = threadIdx.x;

    // zero slabs once: halo rows/cols stay zero for all ic
    for (int i = t; i < 2 * SLABVOL; i += 128) dyn[i] = 0.0f;
    const float* gw = g_w + (size_t)(b * NOCG + ocg) * WBLK;
    for (int i = t; i < WBLK; i += 128) wsh[i] = gw[i];

    // ---- loader: one smem row per thread (t < 66), 10 x 16B cp.async ----
    const float* xb = x + (size_t)(b * CIN) * SP;
    const int lz = t / 22, ly = t - 22 * (t / 22);
    const int gz = z0 - 1 + lz, gy = yh + ly - 1;
    const bool rowok = (t < NROWS) && ((unsigned)gz < D_) && ((unsigned)gy < D_);
    const long grow = (long)gz * 1600 + (long)gy * 40;
    const unsigned sdst0 = (unsigned)__cvta_generic_to_shared(sh)
                         + (unsigned)(t * (SROW * 4) + 16);   // word 4, 16B aligned

    auto prefetch = [&](int ic, int buf) {
        if (!rowok) return;
        const float* src = xb + (size_t)ic * SP + grow;
        unsigned d = sdst0 + (unsigned)buf * (SLABVOL * 4);
        #pragma unroll
        for (int c = 0; c < 10; c++)
            asm volatile("cp.async.cg.shared.global [%0], [%1], 16;"
                         :: "r"(d + c * 16), "l"(src + c * 4));
    };

    // ---- compute setup ----
    const int tyl = t / 5;                // 0..19 local y
    const int xs = (t % 5) * 8;           // 0,8,16,24,32
    const bool active = (t < 100);

    float acc[OCG][8];
    #pragma unroll
    for (int og = 0; og < OCG; og++)
        #pragma unroll
        for (int j = 0; j < 8; j++) acc[og][j] = 0.0f;

    __syncthreads();            // zero-fill visible before first prefetch
    prefetch(0, 0);
    asm volatile("cp.async.commit_group;");

    for (int ic = 0; ic < CIN; ic++) {
        __syncthreads();
        if (ic + 1 < CIN) prefetch(ic + 1, (ic + 1) & 1);
        asm volatile("cp.async.commit_group;");
        asm volatile("cp.async.wait_group 1;");
        __syncthreads();

        if (active) {
            const float* S = sh + (ic & 1) * SLABVOL;
            const float* W = wsh + ic * WICS;   // [ky][zz][kx][oc4]
            #pragma unroll 1
            for (int ky = 0; ky < 3; ky++) {
                #pragma unroll
                for (int zz = 0; zz < 3; zz++) {
                    const float* rowp = S + (zz * 22 + tyl + ky) * SROW + 3 + xs;
                    float f[10];
                    f[0] = rowp[0];
                    float4 a = *(const float4*)(rowp + 1);   // 16B aligned
                    float4 c4 = *(const float4*)(rowp + 5);
                    f[1] = a.x; f[2] = a.y; f[3] = a.z; f[4] = a.w;
                    f[5] = c4.x; f[6] = c4.y; f[7] = c4.z; f[8] = c4.w;
                    f[9] = rowp[9];
                    #pragma unroll
                    for (int kx = 0; kx < 3; kx++) {
                        float4 w4 = *(const float4*)(W + ((ky * 3 + zz) * 3 + kx) * 4);
                        #pragma unroll
                        for (int j = 0; j < 8; j++) {
                            acc[0][j] = fmaf(w4.x, f[j + kx], acc[0][j]);
                            acc[1][j] = fmaf(w4.y, f[j + kx], acc[1][j]);
                            acc[2][j] = fmaf(w4.z, f[j + kx], acc[2][j]);
                            acc[3][j] = fmaf(w4.w, f[j + kx], acc[3][j]);
                        }
                    }
                }
            }
        }
    }

    // ---- epilogue: bias, store y, BN partial sums (per og) ----
    float s1[OCG], s2[OCG];
    #pragma unroll
    for (int og = 0; og < OCG; og++) { s1[og] = 0.0f; s2[og] = 0.0f; }

    if (active) {
        const int ty = yh + tyl;
        #pragma unroll
        for (int og = 0; og < OCG; og++) {
            const int oc = ocg * OCG + og;
            const float bias = g_bias[b * COUT + oc];
            float* yp = g_y + (size_t)(b * COUT + oc) * SP + z0 * 1600 + ty * 40 + xs;
            float4 q0, q1; float v;
            v = acc[og][0] + bias; s1[og] += v; s2[og] = fmaf(v, v, s2[og]); q0.x = v;
            v = acc[og][1] + bias; s1[og] += v; s2[og] = fmaf(v, v, s2[og]); q0.y = v;
            v = acc[og][2] + bias; s1[og] += v; s2[og] = fmaf(v, v, s2[og]); q0.z = v;
            v = acc[og][3] + bias; s1[og] += v; s2[og] = fmaf(v, v, s2[og]); q0.w = v;
            v = acc[og][4] + bias; s1[og] += v; s2[og] = fmaf(v, v, s2[og]); q1.x = v;
            v = acc[og][5] + bias; s1[og] += v; s2[og] = fmaf(v, v, s2[og]); q1.y = v;
            v = acc[og][6] + bias; s1[og] += v; s2[og] = fmaf(v, v, s2[og]); q1.z = v;
            v = acc[og][7] + bias; s1[og] += v; s2[og] = fmaf(v, v, s2[og]); q1.w = v;
            *(float4*)yp       = q0;
            *(float4*)(yp + 4) = q1;
        }
    }
    #pragma unroll
    for (int og = 0; og < OCG; og++) {
        #pragma unroll
        for (int o = 16; o > 0; o >>= 1) {
            s1[og] += __shfl_down_sync(0xffffffff, s1[og], o);
            s2[og] += __shfl_down_sync(0xffffffff, s2[og], o);
        }
    }
    const int wid = t >> 5, lane = t & 31;    // 4 warps
    __syncthreads();
    if (lane == 0) {
        #pragma unroll
        for (int og = 0; og < OCG; og++) {
            red[og * 4 + wid]      = s1[og];
            red[16 + og * 4 + wid] = s2[og];
        }
    }
    __syncthreads();
    if (t < OCG) {
        float a = 0.0f, q = 0.0f;
        #pragma unroll
        for (int i = 0; i < 4; i++) { a += red[t * 4 + i]; q += red[16 + t * 4 + i]; }
        atomicAdd(&g_sum[ocg * OCG + t], a);
        atomicAdd(&g_sumsq[ocg * OCG + t], q);
    }
}

// ---------------------------------------------------------------------------
// Kernel 3: finalize BN -> per-channel scale/shift
// ---------------------------------------------------------------------------
__global__ void k_stats(const float* __restrict__ gamma,
                        const float* __restrict__ beta) {
    int c = threadIdx.x;
    if (c < COUT) {
        const float n = (float)(B_ * SP);
        float mean = g_sum[c] / n;
        float var  = g_sumsq[c] / n - mean * mean;
        float sc = gamma[c] * rsqrtf(var + 1e-5f);
        g_scale[c] = sc;
        g_shift[c] = beta[c] - mean * sc;
    }
}

// ---------------------------------------------------------------------------
// Kernel 4: affine + LeakyReLU + nearest upsample x2; float2 in, 4x float4 out
// ---------------------------------------------------------------------------
__global__ void __launch_bounds__(256)
k_up(float* __restrict__ out) {
    int idx = blockIdx.x * blockDim.x + threadIdx.x;  // over YTOT/2
    if (idx >= YTOT / 2) return;
    int i2 = idx * 2;
    int xw = i2 % 40;                 // even
    int rest = i2 / 40;
    int yw = rest % 40; rest /= 40;
    int zw = rest % 40; rest /= 40;
    int c  = rest % COUT;
    int b  = rest / COUT;

    float2 v = *(const float2*)&g_y[i2];
    float sc = g_scale[c], sf = g_shift[c];
    float a0 = fmaf(sc, v.x, sf); a0 = (a0 >= 0.0f) ? a0 : 0.1f * a0;
    float a1 = fmaf(sc, v.y, sf); a1 = (a1 >= 0.0f) ? a1 : 0.1f * a1;
    float4 p = make_float4(a0, a0, a1, a1);

    size_t base = ((size_t)(b * COUT + c) * 512000u)
                + (size_t)(2 * zw) * 6400u + (size_t)(2 * yw) * 80u + (size_t)(2 * xw);
    float4* o4 = (float4*)(out + base);
    o4[0]    = p;    // (2z,   2y  )
    o4[20]   = p;    // (2z,   2y+1)
    o4[1600] = p;    // (2z+1, 2y  )
    o4[1620] = p;    // (2z+1, 2y+1)
}

// ---------------------------------------------------------------------------
extern "C" void kernel_launch(void* const* d_in, const int* in_sizes, int n_in,
                              void* d_out, int out_size) {
    const float* x     = (const float*)d_in[0];
    const float* emb   = (const float*)d_in[1];
    const float* rw    = (const float*)d_in[2];
    const float* rb    = (const float*)d_in[3];
    const float* ek    = (const float*)d_in[4];
    const float* eb    = (const float*)d_in[5];
    const float* gamma = (const float*)d_in[6];
    const float* beta  = (const float*)d_in[7];
    float* out = (float*)d_out;

    k_route<<<(B_ * NOCG * WBLK + 255) / 256, 256>>>(emb, rw, rb, ek, eb);

    size_t shbytes = (size_t)(2 * SLABVOL + WBLK + 32) * sizeof(float);  // ~39.4 KB
    cudaFuncSetAttribute(k_conv, cudaFuncAttributeMaxDynamicSharedMemorySize, (int)shbytes);
    dim3 gconv(2 * D_, NOCG, B_);
    k_conv<<<gconv, 128, shbytes>>>(x);

    k_stats<<<1, 32>>>(gamma, beta);

    k_up<<<(YTOT / 2 + 255) / 256, 256>>>(out);
}

// round 10
// speedup vs baseline: 1.5215x; 1.1414x over previous
#include <cuda_runtime.h>
#include <math.h>

#define B_    2
#define CIN   32
#define COUT  32
#define D_    40
#define E_    3
#define SP    (D_*D_*D_)          // 64000
#define YTOT  (B_*COUT*SP)        // 4,096,000
#define OCG   4                   // output channels per block
#define NOCG  (COUT/OCG)          // 8
#define ZT    2                   // z-outputs per block
#define YT    8                   // y-rows per block
#define SROW  48                  // padded smem row stride (floats)
#define NROWS ((ZT+2)*(YT+2))     // 40 rows (4 z-planes x 10 y-rows)
#define SLABVOL (NROWS*SROW)      // 1920 floats
#define WBLK  (CIN*27*OCG)        // 3456 weights per block
#define WICS  (27*OCG)            // 108 weights per ic
#define NTHR  160

// ---- scratch (device globals; no runtime allocation) ----
__device__ float g_w[B_*NOCG*WBLK];     // [b][ocg][ic][ky][dz][kx][oc4]
__device__ float g_bias[B_*COUT];
__device__ float g_y[YTOT];             // pre-upsample activations (16.4 MB)
__device__ float g_sum[COUT];
__device__ float g_sumsq[COUT];
__device__ float g_scale[COUT];
__device__ float g_shift[COUT];

// ---------------------------------------------------------------------------
// Kernel 1: routing + combined weights (blocked layout) + bias, zero stats
// ---------------------------------------------------------------------------
__global__ void k_route(const float* __restrict__ emb,
                        const float* __restrict__ rw,
                        const float* __restrict__ rb,
                        const float* __restrict__ ek,
                        const float* __restrict__ eb) {
    float r[B_][E_];
    #pragma unroll
    for (int b = 0; b < B_; b++)
        #pragma unroll
        for (int e = 0; e < E_; e++) {
            float t = fmaf(emb[b], rw[e], rb[e]);
            r[b][e] = 1.0f / (1.0f + expf(-t));
        }

    int idx = blockIdx.x * blockDim.x + threadIdx.x;
    const int TOT = B_ * NOCG * WBLK;   // 55296
    if (idx < TOT) {
        int rr = idx;
        int og = rr & 3;  rr >>= 2;
        int kx = rr % 3;  rr /= 3;
        int dz = rr % 3;  rr /= 3;
        int ky = rr % 3;  rr /= 3;
        int ic = rr % CIN; rr /= CIN;
        int ocg = rr % NOCG;
        int b   = rr / NOCG;
        int oc  = ocg * OCG + og;
        int tap = dz * 9 + ky * 3 + kx;
        float s = 0.0f;
        #pragma unroll
        for (int e = 0; e < E_; e++)
            s = fmaf(r[b][e], ek[((e * COUT + oc) * CIN + ic) * 27 + tap], s);
        g_w[idx] = s;
    }
    if (idx < B_ * COUT) {
        int b = idx / COUT, o = idx - b * COUT;
        float s = 0.0f;
        #pragma unroll
        for (int e = 0; e < E_; e++) s = fmaf(r[b][e], eb[e * COUT + o], s);
        g_bias[idx] = s;
    }
    if (idx < COUT) { g_sum[idx] = 0.0f; g_sumsq[idx] = 0.0f; }
}

// ---------------------------------------------------------------------------
// Kernel 2: direct 3x3x3 conv, 4 oc per block, tile 2z x 8y x 40x.
//   160 threads = 5 FULL warps, every lane computes 4x (zero lane waste).
//   thread: k = t%10 (x-tile of 4), ly = (t/10)%8, tz = t/80.
// grid = (100 [zt*5+yt], 8 ocg, 2 b) = 1600 blocks
// ---------------------------------------------------------------------------
__global__ void __launch_bounds__(NTHR, 5)
k_conv(const float* __restrict__ x) {
    extern __shared__ float dyn[];
    float* sh  = dyn;                    // [2][SLABVOL]
    float* wsh = dyn + 2 * SLABVOL;      // [WBLK]
    float* red = wsh + WBLK;             // [48]

    const int zt  = blockIdx.x / 5;             // 0..19
    const int yt  = blockIdx.x - 5 * (blockIdx.x / 5);  // 0..4
    const int z0  = zt * ZT;
    const int y0  = yt * YT;
    const int ocg = blockIdx.y;                 // 0..7
    const int b   = blockIdx.z;                 // 0..1
    const int t   = threadIdx.x;

    // zero slabs once: halo rows/cols stay zero for all ic
    for (int i = t; i < 2 * SLABVOL; i += NTHR) dyn[i] = 0.0f;
    const float* gw = g_w + (size_t)(b * NOCG + ocg) * WBLK;
    for (int i = t; i < WBLK; i += NTHR) wsh[i] = gw[i];

    // ---- loader: 2 threads per row (t < 80), 5 x 16B cp.async each ----
    const float* xb = x + (size_t)(b * CIN) * SP;
    const int lrow = t >> 1;                   // 0..39 (t<80)
    const int half = t & 1;                    // 0/1: words 4..23 / 24..43
    const int lz = lrow / 10, ly2 = lrow - 10 * (lrow / 10);
    const int gz = z0 - 1 + lz, gy = y0 - 1 + ly2;
    const bool rowok = (t < 80) && ((unsigned)gz < D_) && ((unsigned)gy < D_);
    const long grow = (long)gz * 1600 + (long)gy * 40 + 20 * half;
    const unsigned sdst0 = (unsigned)__cvta_generic_to_shared(sh)
                         + (unsigned)(lrow * (SROW * 4) + 16 + 80 * half);

    auto prefetch = [&](int ic, int buf) {
        if (!rowok) return;
        const float* src = xb + (size_t)ic * SP + grow;
        unsigned d = sdst0 + (unsigned)buf * (SLABVOL * 4);
        #pragma unroll
        for (int c = 0; c < 5; c++)
            asm volatile("cp.async.cg.shared.global [%0], [%1], 16;"
                         :: "r"(d + c * 16), "l"(src + c * 4));
    };

    // ---- compute setup: all 160 threads compute ----
    const int k  = t % 10;                 // x-tile: outputs x = 4k..4k+3
    const int lyc = (t / 10) % 8;          // local y
    const int tz  = t / 80;                // 0/1 local z

    float acc[OCG][4];
    #pragma unroll
    for (int og = 0; og < OCG; og++)
        #pragma unroll
        for (int j = 0; j < 4; j++) acc[og][j] = 0.0f;

    __syncthreads();            // zero-fill visible before first prefetch
    prefetch(0, 0);
    asm volatile("cp.async.commit_group;");

    const int rbase = 2 + 4 * k;           // even word: 4x LDS.64, uniform

    for (int ic = 0; ic < CIN; ic++) {
        __syncthreads();
        if (ic + 1 < CIN) prefetch(ic + 1, (ic + 1) & 1);
        asm volatile("cp.async.commit_group;");
        asm volatile("cp.async.wait_group 1;");
        __syncthreads();

        const float* S = sh + (ic & 1) * SLABVOL;
        const float* W = wsh + ic * WICS;   // [ky][dz][kx][oc4]
        #pragma unroll 1
        for (int ky = 0; ky < 3; ky++) {
            #pragma unroll
            for (int dz = 0; dz < 3; dz++) {
                const int row = (tz + dz) * 10 + lyc + ky;
                const float* rowp = S + row * SROW + rbase;
                float2 p0 = *(const float2*)(rowp);
                float2 p1 = *(const float2*)(rowp + 2);
                float2 p2 = *(const float2*)(rowp + 4);
                float2 p3 = *(const float2*)(rowp + 6);
                // f[i] = window value i (input x = 4k-1+i), i=0..5
                float f[6];
                f[0] = p0.y; f[1] = p1.x; f[2] = p1.y;
                f[3] = p2.x; f[4] = p2.y; f[5] = p3.x;
                #pragma unroll
                for (int kx = 0; kx < 3; kx++) {
                    float4 w4 = *(const float4*)(W + ((ky * 3 + dz) * 3 + kx) * 4);
                    #pragma unroll
                    for (int j = 0; j < 4; j++) {
                        acc[0][j] = fmaf(w4.x, f[j + kx], acc[0][j]);
                        acc[1][j] = fmaf(w4.y, f[j + kx], acc[1][j]);
                        acc[2][j] = fmaf(w4.z, f[j + kx], acc[2][j]);
                        acc[3][j] = fmaf(w4.w, f[j + kx], acc[3][j]);
                    }
                }
            }
        }
    }

    // ---- epilogue: bias, store y, BN partial sums (per og) ----
    float s1[OCG], s2[OCG];
    #pragma unroll
    for (int og = 0; og < OCG; og++) { s1[og] = 0.0f; s2[og] = 0.0f; }

    {
        const int zo = z0 + tz, yo = y0 + lyc, xo = 4 * k;
        #pragma unroll
        for (int og = 0; og < OCG; og++) {
            const int oc = ocg * OCG + og;
            const float bias = g_bias[b * COUT + oc];
            float* yp = g_y + (size_t)(b * COUT + oc) * SP
                      + zo * 1600 + yo * 40 + xo;
            float4 q; float v;
            v = acc[og][0] + bias; s1[og] += v; s2[og] = fmaf(v, v, s2[og]); q.x = v;
            v = acc[og][1] + bias; s1[og] += v; s2[og] = fmaf(v, v, s2[og]); q.y = v;
            v = acc[og][2] + bias; s1[og] += v; s2[og] = fmaf(v, v, s2[og]); q.z = v;
            v = acc[og][3] + bias; s1[og] += v; s2[og] = fmaf(v, v, s2[og]); q.w = v;
            *(float4*)yp = q;   // xo multiple of 4 -> 16B aligned
        }
    }
    #pragma unroll
    for (int og = 0; og < OCG; og++) {
        #pragma unroll
        for (int o = 16; o > 0; o >>= 1) {
            s1[og] += __shfl_down_sync(0xffffffff, s1[og], o);
            s2[og] += __shfl_down_sync(0xffffffff, s2[og], o);
        }
    }
    const int wid = t >> 5, lane = t & 31;    // 5 warps
    __syncthreads();
    if (lane == 0) {
        #pragma unroll
        for (int og = 0; og < OCG; og++) {
            red[og * 5 + wid]      = s1[og];
            red[24 + og * 5 + wid] = s2[og];
        }
    }
    __syncthreads();
    if (t < OCG) {
        float a = 0.0f, q = 0.0f;
        #pragma unroll
        for (int i = 0; i < 5; i++) { a += red[t * 5 + i]; q += red[24 + t * 5 + i]; }
        atomicAdd(&g_sum[ocg * OCG + t], a);
        atomicAdd(&g_sumsq[ocg * OCG + t], q);
    }
}

// ---------------------------------------------------------------------------
// Kernel 3: finalize BN -> per-channel scale/shift
// ---------------------------------------------------------------------------
__global__ void k_stats(const float* __restrict__ gamma,
                        const float* __restrict__ beta) {
    int c = threadIdx.x;
    if (c < COUT) {
        const float n = (float)(B_ * SP);
        float mean = g_sum[c] / n;
        float var  = g_sumsq[c] / n - mean * mean;
        float sc = gamma[c] * rsqrtf(var + 1e-5f);
        g_scale[c] = sc;
        g_shift[c] = beta[c] - mean * sc;
    }
}

// ---------------------------------------------------------------------------
// Kernel 4: affine + LeakyReLU + nearest upsample x2; float2 in, 4x float4 out
// ---------------------------------------------------------------------------
__global__ void __launch_bounds__(256)
k_up(float* __restrict__ out) {
    int idx = blockIdx.x * blockDim.x + threadIdx.x;  // over YTOT/2
    if (idx >= YTOT / 2) return;
    int i2 = idx * 2;
    int xw = i2 % 40;                 // even
    int rest = i2 / 40;
    int yw = rest % 40; rest /= 40;
    int zw = rest % 40; rest /= 40;
    int c  = rest % COUT;
    int b  = rest / COUT;

    float2 v = *(const float2*)&g_y[i2];
    float sc = g_scale[c], sf = g_shift[c];
    float a0 = fmaf(sc, v.x, sf); a0 = (a0 >= 0.0f) ? a0 : 0.1f * a0;
    float a1 = fmaf(sc, v.y, sf); a1 = (a1 >= 0.0f) ? a1 : 0.1f * a1;
    float4 p = make_float4(a0, a0, a1, a1);

    size_t base = ((size_t)(b * COUT + c) * 512000u)
                + (size_t)(2 * zw) * 6400u + (size_t)(2 * yw) * 80u + (size_t)(2 * xw);
    float4* o4 = (float4*)(out + base);
    o4[0]    = p;    // (2z,   2y  )
    o4[20]   = p;    // (2z,   2y+1)
    o4[1600] = p;    // (2z+1, 2y  )
    o4[1620] = p;    // (2z+1, 2y+1)
}

// ---------------------------------------------------------------------------
extern "C" void kernel_launch(void* const* d_in, const int* in_sizes, int n_in,
                              void* d_out, int out_size) {
    const float* x     = (const float*)d_in[0];
    const float* emb   = (const float*)d_in[1];
    const float* rw    = (const float*)d_in[2];
    const float* rb    = (const float*)d_in[3];
    const float* ek    = (const float*)d_in[4];
    const float* eb    = (const float*)d_in[5];
    const float* gamma = (const float*)d_in[6];
    const float* beta  = (const float*)d_in[7];
    float* out = (float*)d_out;

    k_route<<<(B_ * NOCG * WBLK + 255) / 256, 256>>>(emb, rw, rb, ek, eb);

    size_t shbytes = (size_t)(2 * SLABVOL + WBLK + 48) * sizeof(float);  // ~29.5 KB
    cudaFuncSetAttribute(k_conv, cudaFuncAttributeMaxDynamicSharedMemorySize, (int)shbytes);
    dim3 gconv(100, NOCG, B_);
    k_conv<<<gconv, NTHR, shbytes>>>(x);

    k_stats<<<1, 32>>>(gamma, beta);

    k_up<<<(YTOT / 2 + 255) / 256, 256>>>(out);
}

// round 11
// speedup vs baseline: 1.5217x; 1.0001x over previous
#include <cuda_runtime.h>
#include <math.h>

#define B_    2
#define CIN   32
#define COUT  32
#define D_    40
#define E_    3
#define SP    (D_*D_*D_)          // 64000
#define YTOT  (B_*COUT*SP)        // 4,096,000
#define OCG   4                   // output channels per block
#define NOCG  (COUT/OCG)          // 8
#define ZT    2                   // z-outputs per block
#define YT    8                   // y-rows per block
#define SROW  48                  // padded smem row stride (floats)
#define NROWS ((ZT+2)*(YT+2))     // 40 rows (4 z-planes x 10 y-rows)
#define SLABVOL (NROWS*SROW)      // 1920 floats
#define WBLK  (CIN*27*OCG)        // 3456 weights per block
#define WICS  (27*OCG)            // 108 weights per ic
#define NTHR  160

// ---- scratch (device globals; no runtime allocation) ----
__device__ float g_w[B_*NOCG*WBLK];     // [b][ocg][ic][ky][dz][kx][oc4]
__device__ float g_bias[B_*COUT];
__device__ float g_y[YTOT];             // pre-upsample activations (16.4 MB)
__device__ float g_sum[COUT];
__device__ float g_sumsq[COUT];
__device__ float g_scale[COUT];
__device__ float g_shift[COUT];

// ---------------------------------------------------------------------------
// Kernel 1: routing + combined weights (blocked layout) + bias, zero stats
// ---------------------------------------------------------------------------
__global__ void k_route(const float* __restrict__ emb,
                        const float* __restrict__ rw,
                        const float* __restrict__ rb,
                        const float* __restrict__ ek,
                        const float* __restrict__ eb) {
    float r[B_][E_];
    #pragma unroll
    for (int b = 0; b < B_; b++)
        #pragma unroll
        for (int e = 0; e < E_; e++) {
            float t = fmaf(emb[b], rw[e], rb[e]);
            r[b][e] = 1.0f / (1.0f + expf(-t));
        }

    int idx = blockIdx.x * blockDim.x + threadIdx.x;
    const int TOT = B_ * NOCG * WBLK;   // 55296
    if (idx < TOT) {
        int rr = idx;
        int og = rr & 3;  rr >>= 2;
        int kx = rr % 3;  rr /= 3;
        int dz = rr % 3;  rr /= 3;
        int ky = rr % 3;  rr /= 3;
        int ic = rr % CIN; rr /= CIN;
        int ocg = rr % NOCG;
        int b   = rr / NOCG;
        int oc  = ocg * OCG + og;
        int tap = dz * 9 + ky * 3 + kx;
        float s = 0.0f;
        #pragma unroll
        for (int e = 0; e < E_; e++)
            s = fmaf(r[b][e], ek[((e * COUT + oc) * CIN + ic) * 27 + tap], s);
        g_w[idx] = s;
    }
    if (idx < B_ * COUT) {
        int b = idx / COUT, o = idx - b * COUT;
        float s = 0.0f;
        #pragma unroll
        for (int e = 0; e < E_; e++) s = fmaf(r[b][e], eb[e * COUT + o], s);
        g_bias[idx] = s;
    }
    if (idx < COUT) { g_sum[idx] = 0.0f; g_sumsq[idx] = 0.0f; }
}

// ---------------------------------------------------------------------------
// Kernel 2: direct 3x3x3 conv, 4 oc per block, tile 2z x 8y x 40x.
//   160 threads = 5 FULL warps, every lane computes 4x (zero lane waste).
//   thread: k = t%10 (x-tile of 4), ly = (t/10)%8, tz = t/80.
// grid = (100 [zt*5+yt], 8 ocg, 2 b) = 1600 blocks
// ---------------------------------------------------------------------------
__global__ void __launch_bounds__(NTHR, 5)
k_conv(const float* __restrict__ x) {
    extern __shared__ float dyn[];
    float* sh  = dyn;                    // [2][SLABVOL]
    float* wsh = dyn + 2 * SLABVOL;      // [WBLK]
    float* red = wsh + WBLK;             // [48]

    const int zt  = blockIdx.x / 5;             // 0..19
    const int yt  = blockIdx.x - 5 * (blockIdx.x / 5);  // 0..4
    const int z0  = zt * ZT;
    const int y0  = yt * YT;
    const int ocg = blockIdx.y;                 // 0..7
    const int b   = blockIdx.z;                 // 0..1
    const int t   = threadIdx.x;

    // zero slabs once: halo rows/cols stay zero for all ic
    for (int i = t; i < 2 * SLABVOL; i += NTHR) dyn[i] = 0.0f;
    const float* gw = g_w + (size_t)(b * NOCG + ocg) * WBLK;
    for (int i = t; i < WBLK; i += NTHR) wsh[i] = gw[i];

    // ---- loader: 2 threads per row (t < 80), 5 x 16B cp.async each ----
    const float* xb = x + (size_t)(b * CIN) * SP;
    const int lrow = t >> 1;                   // 0..39 (t<80)
    const int half = t & 1;                    // 0/1: words 4..23 / 24..43
    const int lz = lrow / 10, ly2 = lrow - 10 * (lrow / 10);
    const int gz = z0 - 1 + lz, gy = y0 - 1 + ly2;
    const bool rowok = (t < 80) && ((unsigned)gz < D_) && ((unsigned)gy < D_);
    const long grow = (long)gz * 1600 + (long)gy * 40 + 20 * half;
    const unsigned sdst0 = (unsigned)__cvta_generic_to_shared(sh)
                         + (unsigned)(lrow * (SROW * 4) + 16 + 80 * half);

    auto prefetch = [&](int ic, int buf) {
        if (!rowok) return;
        const float* src = xb + (size_t)ic * SP + grow;
        unsigned d = sdst0 + (unsigned)buf * (SLABVOL * 4);
        #pragma unroll
        for (int c = 0; c < 5; c++)
            asm volatile("cp.async.cg.shared.global [%0], [%1], 16;"
                         :: "r"(d + c * 16), "l"(src + c * 4));
    };

    // ---- compute setup: all 160 threads compute ----
    const int k  = t % 10;                 // x-tile: outputs x = 4k..4k+3
    const int lyc = (t / 10) % 8;          // local y
    const int tz  = t / 80;                // 0/1 local z

    float acc[OCG][4];
    #pragma unroll
    for (int og = 0; og < OCG; og++)
        #pragma unroll
        for (int j = 0; j < 4; j++) acc[og][j] = 0.0f;

    __syncthreads();            // zero-fill visible before first prefetch
    prefetch(0, 0);
    asm volatile("cp.async.commit_group;");

    const int rbase = 2 + 4 * k;           // even word: 4x LDS.64, uniform

    for (int ic = 0; ic < CIN; ic++) {
        __syncthreads();
        if (ic + 1 < CIN) prefetch(ic + 1, (ic + 1) & 1);
        asm volatile("cp.async.commit_group;");
        asm volatile("cp.async.wait_group 1;");
        __syncthreads();

        const float* S = sh + (ic & 1) * SLABVOL;
        const float* W = wsh + ic * WICS;   // [ky][dz][kx][oc4]
        #pragma unroll 1
        for (int ky = 0; ky < 3; ky++) {
            #pragma unroll
            for (int dz = 0; dz < 3; dz++) {
                const int row = (tz + dz) * 10 + lyc + ky;
                const float* rowp = S + row * SROW + rbase;
                float2 p0 = *(const float2*)(rowp);
                float2 p1 = *(const float2*)(rowp + 2);
                float2 p2 = *(const float2*)(rowp + 4);
                float2 p3 = *(const float2*)(rowp + 6);
                // f[i] = window value i (input x = 4k-1+i), i=0..5
                float f[6];
                f[0] = p0.y; f[1] = p1.x; f[2] = p1.y;
                f[3] = p2.x; f[4] = p2.y; f[5] = p3.x;
                #pragma unroll
                for (int kx = 0; kx < 3; kx++) {
                    float4 w4 = *(const float4*)(W + ((ky * 3 + dz) * 3 + kx) * 4);
                    #pragma unroll
                    for (int j = 0; j < 4; j++) {
                        acc[0][j] = fmaf(w4.x, f[j + kx], acc[0][j]);
                        acc[1][j] = fmaf(w4.y, f[j + kx], acc[1][j]);
                        acc[2][j] = fmaf(w4.z, f[j + kx], acc[2][j]);
                        acc[3][j] = fmaf(w4.w, f[j + kx], acc[3][j]);
                    }
                }
            }
        }
    }

    // ---- epilogue: bias, store y, BN partial sums (per og) ----
    float s1[OCG], s2[OCG];
    #pragma unroll
    for (int og = 0; og < OCG; og++) { s1[og] = 0.0f; s2[og] = 0.0f; }

    {
        const int zo = z0 + tz, yo = y0 + lyc, xo = 4 * k;
        #pragma unroll
        for (int og = 0; og < OCG; og++) {
            const int oc = ocg * OCG + og;
            const float bias = g_bias[b * COUT + oc];
            float* yp = g_y + (size_t)(b * COUT + oc) * SP
                      + zo * 1600 + yo * 40 + xo;
            float4 q; float v;
            v = acc[og][0] + bias; s1[og] += v; s2[og] = fmaf(v, v, s2[og]); q.x = v;
            v = acc[og][1] + bias; s1[og] += v; s2[og] = fmaf(v, v, s2[og]); q.y = v;
            v = acc[og][2] + bias; s1[og] += v; s2[og] = fmaf(v, v, s2[og]); q.z = v;
            v = acc[og][3] + bias; s1[og] += v; s2[og] = fmaf(v, v, s2[og]); q.w = v;
            *(float4*)yp = q;   // xo multiple of 4 -> 16B aligned
        }
    }
    #pragma unroll
    for (int og = 0; og < OCG; og++) {
        #pragma unroll
        for (int o = 16; o > 0; o >>= 1) {
            s1[og] += __shfl_down_sync(0xffffffff, s1[og], o);
            s2[og] += __shfl_down_sync(0xffffffff, s2[og], o);
        }
    }
    const int wid = t >> 5, lane = t & 31;    // 5 warps
    __syncthreads();
    if (lane == 0) {
        #pragma unroll
        for (int og = 0; og < OCG; og++) {
            red[og * 5 + wid]      = s1[og];
            red[24 + og * 5 + wid] = s2[og];
        }
    }
    __syncthreads();
    if (t < OCG) {
        float a = 0.0f, q = 0.0f;
        #pragma unroll
        for (int i = 0; i < 5; i++) { a += red[t * 5 + i]; q += red[24 + t * 5 + i]; }
        atomicAdd(&g_sum[ocg * OCG + t], a);
        atomicAdd(&g_sumsq[ocg * OCG + t], q);
    }
}

// ---------------------------------------------------------------------------
// Kernel 3: finalize BN -> per-channel scale/shift
// ---------------------------------------------------------------------------
__global__ void k_stats(const float* __restrict__ gamma,
                        const float* __restrict__ beta) {
    int c = threadIdx.x;
    if (c < COUT) {
        const float n = (float)(B_ * SP);
        float mean = g_sum[c] / n;
        float var  = g_sumsq[c] / n - mean * mean;
        float sc = gamma[c] * rsqrtf(var + 1e-5f);
        g_scale[c] = sc;
        g_shift[c] = beta[c] - mean * sc;
    }
}

// ---------------------------------------------------------------------------
// Kernel 4: affine + LeakyReLU + nearest upsample x2; float2 in, 4x float4 out
// ---------------------------------------------------------------------------
__global__ void __launch_bounds__(256)
k_up(float* __restrict__ out) {
    int idx = blockIdx.x * blockDim.x + threadIdx.x;  // over YTOT/2
    if (idx >= YTOT / 2) return;
    int i2 = idx * 2;
    int xw = i2 % 40;                 // even
    int rest = i2 / 40;
    int yw = rest % 40; rest /= 40;
    int zw = rest % 40; rest /= 40;
    int c  = rest % COUT;
    int b  = rest / COUT;

    float2 v = *(const float2*)&g_y[i2];
    float sc = g_scale[c], sf = g_shift[c];
    float a0 = fmaf(sc, v.x, sf); a0 = (a0 >= 0.0f) ? a0 : 0.1f * a0;
    float a1 = fmaf(sc, v.y, sf); a1 = (a1 >= 0.0f) ? a1 : 0.1f * a1;
    float4 p = make_float4(a0, a0, a1, a1);

    size_t base = ((size_t)(b * COUT + c) * 512000u)
                + (size_t)(2 * zw) * 6400u + (size_t)(2 * yw) * 80u + (size_t)(2 * xw);
    float4* o4 = (float4*)(out + base);
    o4[0]    = p;    // (2z,   2y  )
    o4[20]   = p;    // (2z,   2y+1)
    o4[1600] = p;    // (2z+1, 2y  )
    o4[1620] = p;    // (2z+1, 2y+1)
}

// ---------------------------------------------------------------------------
extern "C" void kernel_launch(void* const* d_in, const int* in_sizes, int n_in,
                              void* d_out, int out_size) {
    const float* x     = (const float*)d_in[0];
    const float* emb   = (const float*)d_in[1];
    const float* rw    = (const float*)d_in[2];
    const float* rb    = (const float*)d_in[3];
    const float* ek    = (const float*)d_in[4];
    const float* eb    = (const float*)d_in[5];
    const float* gamma = (const float*)d_in[6];
    const float* beta  = (const float*)d_in[7];
    float* out = (float*)d_out;

    k_route<<<(B_ * NOCG * WBLK + 255) / 256, 256>>>(emb, rw, rb, ek, eb);

    size_t shbytes = (size_t)(2 * SLABVOL + WBLK + 48) * sizeof(float);  // ~29.5 KB
    cudaFuncSetAttribute(k_conv, cudaFuncAttributeMaxDynamicSharedMemorySize, (int)shbytes);
    dim3 gconv(100, NOCG, B_);
    k_conv<<<gconv, NTHR, shbytes>>>(x);

    k_stats<<<1, 32>>>(gamma, beta);

    k_up<<<(YTOT / 2 + 255) / 256, 256>>>(out);
}